// round 1
// baseline (speedup 1.0000x reference)
#include <cuda_runtime.h>
#include <math.h>

// Problem constants (fixed shapes from the reference)
#define BB 2
#define NN 2048
#define CC 1664
#define HH 16
#define DD 104
#define C3 (3 * CC)          // 4992
#define TOKENS (BB * NN)     // 4096

// ---------------------------------------------------------------------------
// Scratch (no allocations allowed): qkv activations and attention output
// ---------------------------------------------------------------------------
__device__ float g_qkv[(size_t)TOKENS * C3];   // [b,n,3,h,d] = [token][s*C + h*D + d]
__device__ float g_att[(size_t)TOKENS * CC];   // [token][h*D + d]

// ---------------------------------------------------------------------------
// SGEMM: C[M,N] = A[M,K] @ B[K,N] + bias[N]
// BM=BN=128, BK=8, TM=TN=8, 256 threads. Shapes here are always tile-exact.
// ---------------------------------------------------------------------------
__global__ __launch_bounds__(256, 2)
void sgemm_bias_kernel(const float* __restrict__ A,
                       const float* __restrict__ B,
                       const float* __restrict__ bias,
                       float* __restrict__ C,
                       int M, int N, int K) {
    const int BM = 128, BN = 128, BK = 8, TM = 8, TN = 8;
    __shared__ float As[BK * BM];   // transposed: As[k][m]
    __shared__ float Bs[BK * BN];   // Bs[k][n]

    const int tid  = threadIdx.x;
    const int crow = blockIdx.y * BM;
    const int ccol = blockIdx.x * BN;

    const int tr = (tid / 16) * TM;   // 0..120
    const int tc = (tid % 16) * TN;   // 0..120

    // load indices
    const int aRow = tid >> 1;          // 0..127
    const int aCol = (tid & 1) * 4;     // 0 or 4
    const int bRow = tid >> 5;          // 0..7
    const int bCol = (tid & 31) * 4;    // 0..124

    const float* Aptr = A + (size_t)crow * K;
    const float* Bptr = B + ccol;

    float acc[TM][TN];
#pragma unroll
    for (int i = 0; i < TM; ++i)
#pragma unroll
        for (int j = 0; j < TN; ++j) acc[i][j] = 0.0f;

    for (int k0 = 0; k0 < K; k0 += BK) {
        float4 av = *reinterpret_cast<const float4*>(Aptr + (size_t)aRow * K + k0 + aCol);
        As[(aCol + 0) * BM + aRow] = av.x;
        As[(aCol + 1) * BM + aRow] = av.y;
        As[(aCol + 2) * BM + aRow] = av.z;
        As[(aCol + 3) * BM + aRow] = av.w;
        float4 bv = *reinterpret_cast<const float4*>(Bptr + (size_t)(k0 + bRow) * N + bCol);
        *reinterpret_cast<float4*>(&Bs[bRow * BN + bCol]) = bv;
        __syncthreads();

#pragma unroll
        for (int kk = 0; kk < BK; ++kk) {
            float ar[TM], br[TN];
            float4 a0 = *reinterpret_cast<const float4*>(&As[kk * BM + tr]);
            float4 a1 = *reinterpret_cast<const float4*>(&As[kk * BM + tr + 4]);
            ar[0]=a0.x; ar[1]=a0.y; ar[2]=a0.z; ar[3]=a0.w;
            ar[4]=a1.x; ar[5]=a1.y; ar[6]=a1.z; ar[7]=a1.w;
            float4 b0 = *reinterpret_cast<const float4*>(&Bs[kk * BN + tc]);
            float4 b1 = *reinterpret_cast<const float4*>(&Bs[kk * BN + tc + 4]);
            br[0]=b0.x; br[1]=b0.y; br[2]=b0.z; br[3]=b0.w;
            br[4]=b1.x; br[5]=b1.y; br[6]=b1.z; br[7]=b1.w;
#pragma unroll
            for (int i = 0; i < TM; ++i)
#pragma unroll
                for (int j = 0; j < TN; ++j) acc[i][j] += ar[i] * br[j];
        }
        __syncthreads();
    }

#pragma unroll
    for (int i = 0; i < TM; ++i) {
        const size_t r = crow + tr + i;
#pragma unroll
        for (int j = 0; j < TN; ++j) {
            const int c = ccol + tc + j;
            C[r * N + c] = acc[i][j] + bias[c];
        }
    }
}

// ---------------------------------------------------------------------------
// RoPE: one block per token; compute cos/sin (104 dims) from 3D coords,
// apply rotate-half to q and k for all 16 heads, in place in g_qkv.
// ---------------------------------------------------------------------------
__global__ void rope_kernel(const int* __restrict__ coords, float* __restrict__ qkv) {
    const int token = blockIdx.x;
    const int tid = threadIdx.x;   // 128 threads
    __shared__ float cs[DD];
    __shared__ float sn[DD];

    const int c0 = coords[token * 3 + 0];
    const int c1 = coords[token * 3 + 1];
    const int c2 = coords[token * 3 + 2];

    if (tid < DD) {
        const int j = tid;
        int jj, dd, coord;
        if (j < 34)      { const int u = j;      jj = (u < 17) ? u : u - 17; dd = 34; coord = c0; }
        else if (j < 68) { const int u = j - 34; jj = (u < 17) ? u : u - 17; dd = 34; coord = c1; }
        else             { const int u = j - 68; jj = (u < 18) ? u : u - 18; dd = 36; coord = c2; }
        const float inv = powf(10000.0f, -(2.0f * (float)jj) / (float)dd);
        const float ang = (float)coord * inv;
        cs[j] = cosf(ang);
        sn[j] = sinf(ang);
    }
    __syncthreads();

    float* base = qkv + (size_t)token * C3;
    // 2 tensors (q,k) x 16 heads x 52 rotation pairs
    for (int idx = tid; idx < 2 * HH * 52; idx += blockDim.x) {
        const int s   = idx / (HH * 52);
        const int rem = idx % (HH * 52);
        const int h   = rem / 52;
        const int j   = rem % 52;
        float* p = base + (size_t)s * CC + h * DD;
        const float a = p[j];
        const float b = p[j + 52];
        p[j]      = a * cs[j]      - b * sn[j];
        p[j + 52] = b * cs[j + 52] + a * sn[j + 52];
    }
}

// ---------------------------------------------------------------------------
// Flash attention, fp32.  Grid: (N/TQ, H, B).  Block: 256 threads.
// Thread (r, qd): r = tid/4 (row in 64-query tile), qd = tid%4 (26-dim slice).
// Online softmax over 32 k-tiles of 64.
// ---------------------------------------------------------------------------
#define TQ 64
#define TK 64
#define SSLD (TK + 1)

__global__ __launch_bounds__(256, 2)
void attn_kernel(const float* __restrict__ qkv, float* __restrict__ out) {
    extern __shared__ float sm[];
    float* qs = sm;                    // [TQ][104]
    float* ks = qs + TQ * DD;          // [TK][104]
    float* vs = ks + TK * DD;          // [TK][104]
    float* ss = vs + TK * DD;          // [TQ][65]

    const int qb  = blockIdx.x;
    const int h   = blockIdx.y;
    const int b   = blockIdx.z;
    const int tid = threadIdx.x;
    const int r   = tid >> 2;   // 0..63
    const int qd  = tid & 3;    // 0..3

    const size_t rstride = C3;
    const float* qbase = qkv + ((size_t)(b * NN + qb * TQ)) * rstride + h * DD;
    const float* kbase = qkv + ((size_t)(b * NN)) * rstride + CC + h * DD;
    const float* vbase = kbase + CC;

    // load q tile (float4: 104 = 26 * 4)
    for (int idx = tid; idx < TQ * 26; idx += 256) {
        const int rr = idx / 26, d4 = idx % 26;
        reinterpret_cast<float4*>(&qs[rr * DD])[d4] =
            reinterpret_cast<const float4*>(qbase + (size_t)rr * rstride)[d4];
    }
    __syncthreads();

    float qreg[26];
#pragma unroll
    for (int i = 0; i < 26; ++i) qreg[i] = qs[r * DD + qd * 26 + i];

    float orow[26];
#pragma unroll
    for (int i = 0; i < 26; ++i) orow[i] = 0.0f;
    float m = -1e30f, l = 0.0f;
    const float scale = 1.0f / sqrtf((float)DD);

    for (int kt = 0; kt < NN / TK; ++kt) {
        __syncthreads();   // previous tile's vs reads done
        for (int idx = tid; idx < TK * 26; idx += 256) {
            const int rr = idx / 26, d4 = idx % 26;
            reinterpret_cast<float4*>(&ks[rr * DD])[d4] =
                reinterpret_cast<const float4*>(kbase + (size_t)(kt * TK + rr) * rstride)[d4];
            reinterpret_cast<float4*>(&vs[rr * DD])[d4] =
                reinterpret_cast<const float4*>(vbase + (size_t)(kt * TK + rr) * rstride)[d4];
        }
        __syncthreads();

        // scores for this row (each of 4 lanes computes all 64, partial dot + shfl reduce)
        float mloc = m;
        for (int c = 0; c < TK; ++c) {
            const float2* krow = reinterpret_cast<const float2*>(&ks[c * DD + qd * 26]);
            float p = 0.0f;
#pragma unroll
            for (int i = 0; i < 13; ++i) {
                const float2 k2 = krow[i];
                p += qreg[2 * i] * k2.x + qreg[2 * i + 1] * k2.y;
            }
            p += __shfl_xor_sync(0xffffffffu, p, 1);
            p += __shfl_xor_sync(0xffffffffu, p, 2);
            p *= scale;
            if (qd == 0) ss[r * SSLD + c] = p;
            mloc = fmaxf(mloc, p);
        }
        __syncwarp();

        const float alpha = __expf(m - mloc);
        l *= alpha;
#pragma unroll
        for (int i = 0; i < 26; ++i) orow[i] *= alpha;

        for (int c = 0; c < TK; ++c) {
            const float p = __expf(ss[r * SSLD + c] - mloc);
            l += p;
            const float2* vrow = reinterpret_cast<const float2*>(&vs[c * DD + qd * 26]);
#pragma unroll
            for (int i = 0; i < 13; ++i) {
                const float2 v2 = vrow[i];
                orow[2 * i]     += p * v2.x;
                orow[2 * i + 1] += p * v2.y;
            }
        }
        m = mloc;
    }

    const float inv_l = 1.0f / l;
    float* obase = out + ((size_t)(b * NN + qb * TQ + r)) * CC + h * DD + qd * 26;
#pragma unroll
    for (int i = 0; i < 26; ++i) obase[i] = orow[i] * inv_l;
}

// ---------------------------------------------------------------------------
// Launch
// ---------------------------------------------------------------------------
extern "C" void kernel_launch(void* const* d_in, const int* in_sizes, int n_in,
                              void* d_out, int out_size) {
    // Resolve inputs by element count (all distinct) — robust to ordering.
    const float* x = nullptr;       // 6,815,744
    const int*   coords = nullptr;  // 12,288
    const float* qkv_w = nullptr;   // 8,306,688
    const float* qkv_b = nullptr;   // 4,992
    const float* proj_w = nullptr;  // 2,768,896
    const float* proj_b = nullptr;  // 1,664
    for (int i = 0; i < n_in; ++i) {
        switch (in_sizes[i]) {
            case TOKENS * CC:      x      = (const float*)d_in[i]; break;
            case TOKENS * 3:       coords = (const int*)d_in[i];   break;
            case CC * C3:          qkv_w  = (const float*)d_in[i]; break;
            case C3:               qkv_b  = (const float*)d_in[i]; break;
            case CC * CC:          proj_w = (const float*)d_in[i]; break;
            case CC:               proj_b = (const float*)d_in[i]; break;
            default: break;
        }
    }
    float* out = (float*)d_out;

    float* qkv = nullptr;
    float* att = nullptr;
    cudaGetSymbolAddress((void**)&qkv, g_qkv);
    cudaGetSymbolAddress((void**)&att, g_att);

    // 1) QKV GEMM + bias: [4096,1664] @ [1664,4992]
    {
        dim3 grid(C3 / 128, TOKENS / 128);
        sgemm_bias_kernel<<<grid, 256>>>(x, qkv_w, qkv_b, qkv, TOKENS, C3, CC);
    }

    // 2) RoPE in place on q,k
    rope_kernel<<<TOKENS, 128>>>(coords, qkv);

    // 3) Flash attention
    {
        const int smem = (3 * TK * DD + TQ * SSLD) * (int)sizeof(float);  // 96,512 B
        cudaFuncSetAttribute(attn_kernel, cudaFuncAttributeMaxDynamicSharedMemorySize, smem);
        dim3 grid(NN / TQ, HH, BB);
        attn_kernel<<<grid, 256, smem>>>(qkv, att);
    }

    // 4) Output projection + bias: [4096,1664] @ [1664,1664]
    {
        dim3 grid(CC / 128, TOKENS / 128);
        sgemm_bias_kernel<<<grid, 256>>>(att, proj_w, proj_b, out, TOKENS, CC, CC);
    }
}

// round 3
// speedup vs baseline: 1.3479x; 1.3479x over previous
#include <cuda_runtime.h>
#include <cuda_bf16.h>
#include <math.h>
#include <stdint.h>

// Problem constants
#define BB 2
#define NN 2048
#define CC 1664
#define HH 16
#define DD 104
#define C3 (3 * CC)          // 4992
#define TOKENS (BB * NN)     // 4096

// ---------------------------------------------------------------------------
// Scratch (no allocations allowed)
// ---------------------------------------------------------------------------
__device__ __align__(256) float g_qkv[(size_t)TOKENS * C3];
__device__ __align__(256) float g_att[(size_t)TOKENS * CC];
__device__ __align__(256) __nv_bfloat16 g_xh[(size_t)TOKENS * CC];
__device__ __align__(256) __nv_bfloat16 g_xl[(size_t)TOKENS * CC];
__device__ __align__(256) __nv_bfloat16 g_ah[(size_t)TOKENS * CC];
__device__ __align__(256) __nv_bfloat16 g_al[(size_t)TOKENS * CC];
__device__ __align__(256) __nv_bfloat16 g_wqh[(size_t)C3 * CC];   // qkv_w^T [4992][1664]
__device__ __align__(256) __nv_bfloat16 g_wql[(size_t)C3 * CC];
__device__ __align__(256) __nv_bfloat16 g_wph[(size_t)CC * CC];   // proj_w^T [1664][1664]
__device__ __align__(256) __nv_bfloat16 g_wpl[(size_t)CC * CC];

// ---------------------------------------------------------------------------
// Helpers
// ---------------------------------------------------------------------------
__device__ __forceinline__ uint32_t smem_u32(const void* p) {
    uint32_t a;
    asm("{ .reg .u64 t; cvta.to.shared.u64 t, %1; cvt.u32.u64 %0, t; }" : "=r"(a) : "l"(p));
    return a;
}

__device__ __forceinline__ void cp_async16(uint32_t dst, const void* src) {
    asm volatile("cp.async.cg.shared.global [%0], [%1], 16;" :: "r"(dst), "l"(src));
}
__device__ __forceinline__ void cp_commit() {
    asm volatile("cp.async.commit_group;");
}

__device__ __forceinline__ void ldmatrix_x4(uint32_t* r, uint32_t addr) {
    asm volatile("ldmatrix.sync.aligned.m8n8.x4.shared.b16 {%0,%1,%2,%3}, [%4];"
                 : "=r"(r[0]), "=r"(r[1]), "=r"(r[2]), "=r"(r[3]) : "r"(addr));
}
__device__ __forceinline__ void ldmatrix_x2(uint32_t* r, uint32_t addr) {
    asm volatile("ldmatrix.sync.aligned.m8n8.x2.shared.b16 {%0,%1}, [%2];"
                 : "=r"(r[0]), "=r"(r[1]) : "r"(addr));
}
__device__ __forceinline__ void mma_bf16(float* c, const uint32_t* a, const uint32_t* b) {
    asm volatile("mma.sync.aligned.m16n8k16.row.col.f32.bf16.bf16.f32 "
                 "{%0,%1,%2,%3}, {%4,%5,%6,%7}, {%8,%9}, {%0,%1,%2,%3};"
                 : "+f"(c[0]), "+f"(c[1]), "+f"(c[2]), "+f"(c[3])
                 : "r"(a[0]), "r"(a[1]), "r"(a[2]), "r"(a[3]), "r"(b[0]), "r"(b[1]));
}

// ---------------------------------------------------------------------------
// fp32 -> bf16 hi/lo split
// ---------------------------------------------------------------------------
__global__ void convert_split_kernel(const float* __restrict__ src,
                                     __nv_bfloat16* __restrict__ hi,
                                     __nv_bfloat16* __restrict__ lo, int n) {
    for (int i = blockIdx.x * blockDim.x + threadIdx.x; i < n; i += gridDim.x * blockDim.x) {
        const float v = src[i];
        const __nv_bfloat16 h = __float2bfloat16(v);
        hi[i] = h;
        lo[i] = __float2bfloat16(v - __bfloat162float(h));
    }
}

// ---------------------------------------------------------------------------
// W[Kr][Nc] row-major  ->  T[Nc][Kr] bf16 hi/lo
// ---------------------------------------------------------------------------
__global__ void transpose_split_kernel(const float* __restrict__ W,
                                       __nv_bfloat16* __restrict__ Th,
                                       __nv_bfloat16* __restrict__ Tl,
                                       int Kr, int Nc) {
    __shared__ float t[32][33];
    const int x = blockIdx.x * 32 + threadIdx.x;  // N index
    const int y0 = blockIdx.y * 32;               // K base
    for (int j = threadIdx.y; j < 32; j += 8)
        t[j][threadIdx.x] = W[(size_t)(y0 + j) * Nc + x];
    __syncthreads();
    const int ox = y0 + threadIdx.x;              // K index
    const int oy0 = blockIdx.x * 32;              // N base
    for (int j = threadIdx.y; j < 32; j += 8) {
        const float v = t[threadIdx.x][j];
        const __nv_bfloat16 h = __float2bfloat16(v);
        Th[(size_t)(oy0 + j) * Kr + ox] = h;
        Tl[(size_t)(oy0 + j) * Kr + ox] = __float2bfloat16(v - __bfloat162float(h));
    }
}

// ---------------------------------------------------------------------------
// mma.sync GEMM: C[M,N] = (Ah+Al)[M,K] @ (Bh+Bl)[N,K]^T + bias[N]
// bf16 hi/lo 3-term split, fp32 accumulate. BM=BN=128, BK=32, 256 threads.
// Double-buffered cp.async. 8 warps as 2(m) x 4(n), warp tile 64x32.
// smem tile layout: row stride 64B (32 bf16), 16B-chunk swizzle:
//   chunk' = chunk ^ ((row>>1)&3)
// ---------------------------------------------------------------------------
#define TILE_BYTES 8192     // 128 rows * 64B
#define STAGE_BYTES 32768   // 4 tiles

__global__ __launch_bounds__(256, 1)
void mma_gemm_kernel(const __nv_bfloat16* __restrict__ Ah,
                     const __nv_bfloat16* __restrict__ Al,
                     const __nv_bfloat16* __restrict__ Bh,
                     const __nv_bfloat16* __restrict__ Bl,
                     const float* __restrict__ bias,
                     float* __restrict__ Cout,
                     int M, int N, int K) {
    extern __shared__ char smem[];
    const uint32_t sbase = smem_u32(smem);
    const int tid  = threadIdx.x;
    const int lane = tid & 31;
    const int wid  = tid >> 5;
    const int wm   = wid & 1;        // 0..1  (m direction, 64 each)
    const int wn   = wid >> 1;       // 0..3  (n direction, 32 each)
    const int crow = blockIdx.y * 128;
    const int ccol = blockIdx.x * 128;

    const __nv_bfloat16* gsrc[4];
    gsrc[0] = Ah + (size_t)crow * K;
    gsrc[1] = Al + (size_t)crow * K;
    gsrc[2] = Bh + (size_t)ccol * K;
    gsrc[3] = Bl + (size_t)ccol * K;

    // per-thread load coords: each thread does 2 rows x 1 chunk per tile
    const int lc  = tid & 3;          // chunk 0..3
    const int lr0 = tid >> 2;         // row 0..63
    const int lr1 = lr0 + 64;
    const uint32_t sw0 = (uint32_t)((lc ^ ((lr0 >> 1) & 3)) << 4);
    const uint32_t sw1 = (uint32_t)((lc ^ ((lr1 >> 1) & 3)) << 4);

    float acc[4][4][4];
#pragma unroll
    for (int mt = 0; mt < 4; ++mt)
#pragma unroll
        for (int nt = 0; nt < 4; ++nt)
#pragma unroll
            for (int j = 0; j < 4; ++j) acc[mt][nt][j] = 0.0f;

    const int nch = K / 32;

    // ---- stage loader ----
    auto load_stage = [&](int stage, int k0) {
        const uint32_t sb = sbase + (uint32_t)stage * STAGE_BYTES;
#pragma unroll
        for (int t = 0; t < 4; ++t) {
            const __nv_bfloat16* g = gsrc[t];
            cp_async16(sb + t * TILE_BYTES + lr0 * 64 + sw0,
                       g + (size_t)lr0 * K + k0 + lc * 8);
            cp_async16(sb + t * TILE_BYTES + lr1 * 64 + sw1,
                       g + (size_t)lr1 * K + k0 + lc * 8);
        }
        cp_commit();
    };

    load_stage(0, 0);

    // ldmatrix lane-address components
    const int a_lrow   = (lane & 7) + ((lane >> 3) & 1) * 8;   // 0..15
    const int a_lchunk = lane >> 4;                            // 0/1
    const int b_lrow   = lane & 7;
    const int b_lchunk = (lane >> 3) & 1;

    for (int ch = 0; ch < nch; ++ch) {
        if (ch + 1 < nch) {
            load_stage((ch + 1) & 1, (ch + 1) * 32);
            asm volatile("cp.async.wait_group 1;");
        } else {
            asm volatile("cp.async.wait_group 0;");
        }
        __syncthreads();

        const uint32_t sb = sbase + (uint32_t)(ch & 1) * STAGE_BYTES;

#pragma unroll
        for (int ks = 0; ks < 2; ++ks) {
            uint32_t afh[4][4], afl[4][4], bfh[4][2], bfl[4][2];
#pragma unroll
            for (int mt = 0; mt < 4; ++mt) {
                const int row = wm * 64 + mt * 16 + a_lrow;
                const int chn = 2 * ks + a_lchunk;
                const uint32_t addr = sb + (uint32_t)(row * 64)
                                    + (uint32_t)((chn ^ ((row >> 1) & 3)) << 4);
                ldmatrix_x4(afh[mt], addr);
                ldmatrix_x4(afl[mt], addr + TILE_BYTES);
            }
#pragma unroll
            for (int nt = 0; nt < 4; ++nt) {
                const int row = wn * 32 + nt * 8 + b_lrow;
                const int chn = 2 * ks + b_lchunk;
                const uint32_t addr = sb + 2 * TILE_BYTES + (uint32_t)(row * 64)
                                    + (uint32_t)((chn ^ ((row >> 1) & 3)) << 4);
                ldmatrix_x2(bfh[nt], addr);
                ldmatrix_x2(bfl[nt], addr + TILE_BYTES);
            }
#pragma unroll
            for (int mt = 0; mt < 4; ++mt)
#pragma unroll
                for (int nt = 0; nt < 4; ++nt) {
                    mma_bf16(acc[mt][nt], afh[mt], bfh[nt]);
                    mma_bf16(acc[mt][nt], afh[mt], bfl[nt]);
                    mma_bf16(acc[mt][nt], afl[mt], bfh[nt]);
                }
        }
        __syncthreads();
    }

    // epilogue: c-frag m16n8: rows lane>>2 (+8), cols (lane&3)*2 (+1)
    const int erow = lane >> 2;
    const int ecol = (lane & 3) * 2;
#pragma unroll
    for (int mt = 0; mt < 4; ++mt) {
#pragma unroll
        for (int nt = 0; nt < 4; ++nt) {
            const int col = ccol + wn * 32 + nt * 8 + ecol;
            const float b0 = bias[col], b1 = bias[col + 1];
            const int r0 = crow + wm * 64 + mt * 16 + erow;
            float2* p0 = reinterpret_cast<float2*>(Cout + (size_t)r0 * N + col);
            *p0 = make_float2(acc[mt][nt][0] + b0, acc[mt][nt][1] + b1);
            float2* p1 = reinterpret_cast<float2*>(Cout + (size_t)(r0 + 8) * N + col);
            *p1 = make_float2(acc[mt][nt][2] + b0, acc[mt][nt][3] + b1);
        }
    }
}

// ---------------------------------------------------------------------------
// RoPE: one block per token
// ---------------------------------------------------------------------------
__global__ void rope_kernel(const int* __restrict__ coords, float* __restrict__ qkv) {
    const int token = blockIdx.x;
    const int tid = threadIdx.x;
    __shared__ float cs[DD];
    __shared__ float sn[DD];

    const int c0 = coords[token * 3 + 0];
    const int c1 = coords[token * 3 + 1];
    const int c2 = coords[token * 3 + 2];

    if (tid < DD) {
        const int j = tid;
        int jj, dd, coord;
        if (j < 34)      { const int u = j;      jj = (u < 17) ? u : u - 17; dd = 34; coord = c0; }
        else if (j < 68) { const int u = j - 34; jj = (u < 17) ? u : u - 17; dd = 34; coord = c1; }
        else             { const int u = j - 68; jj = (u < 18) ? u : u - 18; dd = 36; coord = c2; }
        const float inv = powf(10000.0f, -(2.0f * (float)jj) / (float)dd);
        const float ang = (float)coord * inv;
        cs[j] = cosf(ang);
        sn[j] = sinf(ang);
    }
    __syncthreads();

    float* base = qkv + (size_t)token * C3;
    for (int idx = tid; idx < 2 * HH * 52; idx += blockDim.x) {
        const int s   = idx / (HH * 52);
        const int rem = idx % (HH * 52);
        const int h   = rem / 52;
        const int j   = rem % 52;
        float* p = base + (size_t)s * CC + h * DD;
        const float a = p[j];
        const float b = p[j + 52];
        p[j]      = a * cs[j]      - b * sn[j];
        p[j + 52] = b * cs[j + 52] + a * sn[j + 52];
    }
}

// ---------------------------------------------------------------------------
// Flash attention, fp32 (unchanged this round)
// ---------------------------------------------------------------------------
#define TQ 64
#define TK 64
#define SSLD (TK + 1)

__global__ __launch_bounds__(256, 2)
void attn_kernel(const float* __restrict__ qkv, float* __restrict__ out) {
    extern __shared__ float sm[];
    float* qs = sm;
    float* ks = qs + TQ * DD;
    float* vs = ks + TK * DD;
    float* ss = vs + TK * DD;

    const int qb  = blockIdx.x;
    const int h   = blockIdx.y;
    const int b   = blockIdx.z;
    const int tid = threadIdx.x;
    const int r   = tid >> 2;
    const int qd  = tid & 3;

    const size_t rstride = C3;
    const float* qbase = qkv + ((size_t)(b * NN + qb * TQ)) * rstride + h * DD;
    const float* kbase = qkv + ((size_t)(b * NN)) * rstride + CC + h * DD;
    const float* vbase = kbase + CC;

    for (int idx = tid; idx < TQ * 26; idx += 256) {
        const int rr = idx / 26, d4 = idx % 26;
        reinterpret_cast<float4*>(&qs[rr * DD])[d4] =
            reinterpret_cast<const float4*>(qbase + (size_t)rr * rstride)[d4];
    }
    __syncthreads();

    float qreg[26];
#pragma unroll
    for (int i = 0; i < 26; ++i) qreg[i] = qs[r * DD + qd * 26 + i];

    float orow[26];
#pragma unroll
    for (int i = 0; i < 26; ++i) orow[i] = 0.0f;
    float m = -1e30f, l = 0.0f;
    const float scale = 1.0f / sqrtf((float)DD);

    for (int kt = 0; kt < NN / TK; ++kt) {
        __syncthreads();
        for (int idx = tid; idx < TK * 26; idx += 256) {
            const int rr = idx / 26, d4 = idx % 26;
            reinterpret_cast<float4*>(&ks[rr * DD])[d4] =
                reinterpret_cast<const float4*>(kbase + (size_t)(kt * TK + rr) * rstride)[d4];
            reinterpret_cast<float4*>(&vs[rr * DD])[d4] =
                reinterpret_cast<const float4*>(vbase + (size_t)(kt * TK + rr) * rstride)[d4];
        }
        __syncthreads();

        float mloc = m;
        for (int c = 0; c < TK; ++c) {
            const float2* krow = reinterpret_cast<const float2*>(&ks[c * DD + qd * 26]);
            float p = 0.0f;
#pragma unroll
            for (int i = 0; i < 13; ++i) {
                const float2 k2 = krow[i];
                p += qreg[2 * i] * k2.x + qreg[2 * i + 1] * k2.y;
            }
            p += __shfl_xor_sync(0xffffffffu, p, 1);
            p += __shfl_xor_sync(0xffffffffu, p, 2);
            p *= scale;
            if (qd == 0) ss[r * SSLD + c] = p;
            mloc = fmaxf(mloc, p);
        }
        __syncwarp();

        const float alpha = __expf(m - mloc);
        l *= alpha;
#pragma unroll
        for (int i = 0; i < 26; ++i) orow[i] *= alpha;

        for (int c = 0; c < TK; ++c) {
            const float p = __expf(ss[r * SSLD + c] - mloc);
            l += p;
            const float2* vrow = reinterpret_cast<const float2*>(&vs[c * DD + qd * 26]);
#pragma unroll
            for (int i = 0; i < 13; ++i) {
                const float2 v2 = vrow[i];
                orow[2 * i]     += p * v2.x;
                orow[2 * i + 1] += p * v2.y;
            }
        }
        m = mloc;
    }

    const float inv_l = 1.0f / l;
    float* obase = out + ((size_t)(b * NN + qb * TQ + r)) * CC + h * DD + qd * 26;
#pragma unroll
    for (int i = 0; i < 26; ++i) obase[i] = orow[i] * inv_l;
}

// ---------------------------------------------------------------------------
// Launch
// ---------------------------------------------------------------------------
extern "C" void kernel_launch(void* const* d_in, const int* in_sizes, int n_in,
                              void* d_out, int out_size) {
    const float* x = nullptr;
    const int*   coords = nullptr;
    const float* qkv_w = nullptr;
    const float* qkv_b = nullptr;
    const float* proj_w = nullptr;
    const float* proj_b = nullptr;
    for (int i = 0; i < n_in; ++i) {
        switch (in_sizes[i]) {
            case TOKENS * CC:      x      = (const float*)d_in[i]; break;
            case TOKENS * 3:       coords = (const int*)d_in[i];   break;
            case CC * C3:          qkv_w  = (const float*)d_in[i]; break;
            case C3:               qkv_b  = (const float*)d_in[i]; break;
            case CC * CC:          proj_w = (const float*)d_in[i]; break;
            case CC:               proj_b = (const float*)d_in[i]; break;
            default: break;
        }
    }
    float* out = (float*)d_out;

    float *qkv, *att;
    __nv_bfloat16 *xh, *xl, *ah, *al, *wqh, *wql, *wph, *wpl;
    cudaGetSymbolAddress((void**)&qkv, g_qkv);
    cudaGetSymbolAddress((void**)&att, g_att);
    cudaGetSymbolAddress((void**)&xh,  g_xh);
    cudaGetSymbolAddress((void**)&xl,  g_xl);
    cudaGetSymbolAddress((void**)&ah,  g_ah);
    cudaGetSymbolAddress((void**)&al,  g_al);
    cudaGetSymbolAddress((void**)&wqh, g_wqh);
    cudaGetSymbolAddress((void**)&wql, g_wql);
    cudaGetSymbolAddress((void**)&wph, g_wph);
    cudaGetSymbolAddress((void**)&wpl, g_wpl);

    const int gemm_smem = 2 * STAGE_BYTES;  // 65536
    cudaFuncSetAttribute(mma_gemm_kernel, cudaFuncAttributeMaxDynamicSharedMemorySize, gemm_smem);

    // 1) split x -> bf16 hi/lo
    convert_split_kernel<<<4096, 256>>>(x, xh, xl, TOKENS * CC);

    // 2) transpose+split qkv_w [1664,4992] -> [4992,1664]
    {
        dim3 grid(C3 / 32, CC / 32);
        transpose_split_kernel<<<grid, dim3(32, 8)>>>(qkv_w, wqh, wql, CC, C3);
    }

    // 3) QKV GEMM on tensor cores
    {
        dim3 grid(C3 / 128, TOKENS / 128);
        mma_gemm_kernel<<<grid, 256, gemm_smem>>>(xh, xl, wqh, wql, qkv_b, qkv,
                                                  TOKENS, C3, CC);
    }

    // 4) RoPE in place on q,k
    rope_kernel<<<TOKENS, 128>>>(coords, qkv);

    // 5) Flash attention
    {
        const int smem = (3 * TK * DD + TQ * SSLD) * (int)sizeof(float);
        cudaFuncSetAttribute(attn_kernel, cudaFuncAttributeMaxDynamicSharedMemorySize, smem);
        dim3 grid(NN / TQ, HH, BB);
        attn_kernel<<<grid, 256, smem>>>(qkv, att);
    }

    // 6) split attention output
    convert_split_kernel<<<4096, 256>>>(att, ah, al, TOKENS * CC);

    // 7) transpose+split proj_w [1664,1664]
    {
        dim3 grid(CC / 32, CC / 32);
        transpose_split_kernel<<<grid, dim3(32, 8)>>>(proj_w, wph, wpl, CC, CC);
    }

    // 8) Projection GEMM on tensor cores
    {
        dim3 grid(CC / 128, TOKENS / 128);
        mma_gemm_kernel<<<grid, 256, gemm_smem>>>(ah, al, wph, wpl, proj_b, out,
                                                  TOKENS, CC, CC);
    }
}

// round 5
// speedup vs baseline: 4.1189x; 3.0558x over previous
#include <cuda_runtime.h>
#include <cuda_bf16.h>
#include <math.h>
#include <stdint.h>

// Problem constants
#define BB 2
#define NN 2048
#define CC 1664
#define HH 16
#define DD 104
#define C3 (3 * CC)          // 4992
#define TOKENS (BB * NN)     // 4096

// ---------------------------------------------------------------------------
// Scratch (no allocations allowed)
// ---------------------------------------------------------------------------
__device__ __align__(256) float g_qkv[(size_t)TOKENS * C3];
__device__ __align__(256) __nv_bfloat16 g_xh[(size_t)TOKENS * CC];
__device__ __align__(256) __nv_bfloat16 g_xl[(size_t)TOKENS * CC];
__device__ __align__(256) __nv_bfloat16 g_ah[(size_t)TOKENS * CC];
__device__ __align__(256) __nv_bfloat16 g_al[(size_t)TOKENS * CC];
__device__ __align__(256) __nv_bfloat16 g_wqh[(size_t)C3 * CC];
__device__ __align__(256) __nv_bfloat16 g_wql[(size_t)C3 * CC];
__device__ __align__(256) __nv_bfloat16 g_wph[(size_t)CC * CC];
__device__ __align__(256) __nv_bfloat16 g_wpl[(size_t)CC * CC];
// attention operand buffers: Q/K padded to 128 dims, V transposed [d][n]
__device__ __align__(256) __nv_bfloat16 g_qh[(size_t)BB * HH * NN * 128];
__device__ __align__(256) __nv_bfloat16 g_ql[(size_t)BB * HH * NN * 128];
__device__ __align__(256) __nv_bfloat16 g_kh[(size_t)BB * HH * NN * 128];
__device__ __align__(256) __nv_bfloat16 g_kl[(size_t)BB * HH * NN * 128];
__device__ __align__(256) __nv_bfloat16 g_vth[(size_t)BB * HH * DD * NN];
__device__ __align__(256) __nv_bfloat16 g_vtl[(size_t)BB * HH * DD * NN];

// ---------------------------------------------------------------------------
// Helpers
// ---------------------------------------------------------------------------
__device__ __forceinline__ uint32_t smem_u32(const void* p) {
    uint32_t a;
    asm("{ .reg .u64 t; cvta.to.shared.u64 t, %1; cvt.u32.u64 %0, t; }" : "=r"(a) : "l"(p));
    return a;
}
__device__ __forceinline__ void cp_async16(uint32_t dst, const void* src) {
    asm volatile("cp.async.cg.shared.global [%0], [%1], 16;" :: "r"(dst), "l"(src));
}
__device__ __forceinline__ void cp_commit() {
    asm volatile("cp.async.commit_group;");
}
__device__ __forceinline__ void ldmatrix_x4(uint32_t* r, uint32_t addr) {
    asm volatile("ldmatrix.sync.aligned.m8n8.x4.shared.b16 {%0,%1,%2,%3}, [%4];"
                 : "=r"(r[0]), "=r"(r[1]), "=r"(r[2]), "=r"(r[3]) : "r"(addr));
}
__device__ __forceinline__ void ldmatrix_x2(uint32_t* r, uint32_t addr) {
    asm volatile("ldmatrix.sync.aligned.m8n8.x2.shared.b16 {%0,%1}, [%2];"
                 : "=r"(r[0]), "=r"(r[1]) : "r"(addr));
}
__device__ __forceinline__ void mma_bf16(float* c, const uint32_t* a, const uint32_t* b) {
    asm volatile("mma.sync.aligned.m16n8k16.row.col.f32.bf16.bf16.f32 "
                 "{%0,%1,%2,%3}, {%4,%5,%6,%7}, {%8,%9}, {%0,%1,%2,%3};"
                 : "+f"(c[0]), "+f"(c[1]), "+f"(c[2]), "+f"(c[3])
                 : "r"(a[0]), "r"(a[1]), "r"(a[2]), "r"(a[3]), "r"(b[0]), "r"(b[1]));
}
__device__ __forceinline__ void pack_hilo(float a, float b, uint32_t& hi, uint32_t& lo) {
    const __nv_bfloat16 ha = __float2bfloat16(a);
    const __nv_bfloat16 hb = __float2bfloat16(b);
    const __nv_bfloat16 la = __float2bfloat16(a - __bfloat162float(ha));
    const __nv_bfloat16 lb = __float2bfloat16(b - __bfloat162float(hb));
    hi = (uint32_t)*reinterpret_cast<const uint16_t*>(&ha) |
         ((uint32_t)*reinterpret_cast<const uint16_t*>(&hb) << 16);
    lo = (uint32_t)*reinterpret_cast<const uint16_t*>(&la) |
         ((uint32_t)*reinterpret_cast<const uint16_t*>(&lb) << 16);
}

// ---------------------------------------------------------------------------
// fp32 -> bf16 hi/lo split
// ---------------------------------------------------------------------------
__global__ void convert_split_kernel(const float* __restrict__ src,
                                     __nv_bfloat16* __restrict__ hi,
                                     __nv_bfloat16* __restrict__ lo, int n) {
    for (int i = blockIdx.x * blockDim.x + threadIdx.x; i < n; i += gridDim.x * blockDim.x) {
        const float v = src[i];
        const __nv_bfloat16 h = __float2bfloat16(v);
        hi[i] = h;
        lo[i] = __float2bfloat16(v - __bfloat162float(h));
    }
}

// ---------------------------------------------------------------------------
// W[Kr][Nc] row-major  ->  T[Nc][Kr] bf16 hi/lo
// ---------------------------------------------------------------------------
__global__ void transpose_split_kernel(const float* __restrict__ W,
                                       __nv_bfloat16* __restrict__ Th,
                                       __nv_bfloat16* __restrict__ Tl,
                                       int Kr, int Nc) {
    __shared__ float t[32][33];
    const int x = blockIdx.x * 32 + threadIdx.x;
    const int y0 = blockIdx.y * 32;
    for (int j = threadIdx.y; j < 32; j += 8)
        t[j][threadIdx.x] = W[(size_t)(y0 + j) * Nc + x];
    __syncthreads();
    const int ox = y0 + threadIdx.x;
    const int oy0 = blockIdx.x * 32;
    for (int j = threadIdx.y; j < 32; j += 8) {
        const float v = t[threadIdx.x][j];
        const __nv_bfloat16 h = __float2bfloat16(v);
        Th[(size_t)(oy0 + j) * Kr + ox] = h;
        Tl[(size_t)(oy0 + j) * Kr + ox] = __float2bfloat16(v - __bfloat162float(h));
    }
}

// ---------------------------------------------------------------------------
// mma.sync GEMM (unchanged)
// ---------------------------------------------------------------------------
#define TILE_BYTES 8192
#define STAGE_BYTES 32768

__global__ __launch_bounds__(256, 1)
void mma_gemm_kernel(const __nv_bfloat16* __restrict__ Ah,
                     const __nv_bfloat16* __restrict__ Al,
                     const __nv_bfloat16* __restrict__ Bh,
                     const __nv_bfloat16* __restrict__ Bl,
                     const float* __restrict__ bias,
                     float* __restrict__ Cout,
                     int M, int N, int K) {
    extern __shared__ char smem[];
    const uint32_t sbase = smem_u32(smem);
    const int tid  = threadIdx.x;
    const int lane = tid & 31;
    const int wid  = tid >> 5;
    const int wm   = wid & 1;
    const int wn   = wid >> 1;
    const int crow = blockIdx.y * 128;
    const int ccol = blockIdx.x * 128;

    const __nv_bfloat16* gsrc[4];
    gsrc[0] = Ah + (size_t)crow * K;
    gsrc[1] = Al + (size_t)crow * K;
    gsrc[2] = Bh + (size_t)ccol * K;
    gsrc[3] = Bl + (size_t)ccol * K;

    const int lc  = tid & 3;
    const int lr0 = tid >> 2;
    const int lr1 = lr0 + 64;
    const uint32_t sw0 = (uint32_t)((lc ^ ((lr0 >> 1) & 3)) << 4);
    const uint32_t sw1 = (uint32_t)((lc ^ ((lr1 >> 1) & 3)) << 4);

    float acc[4][4][4];
#pragma unroll
    for (int mt = 0; mt < 4; ++mt)
#pragma unroll
        for (int nt = 0; nt < 4; ++nt)
#pragma unroll
            for (int j = 0; j < 4; ++j) acc[mt][nt][j] = 0.0f;

    const int nch = K / 32;

    auto load_stage = [&](int stage, int k0) {
        const uint32_t sb = sbase + (uint32_t)stage * STAGE_BYTES;
#pragma unroll
        for (int t = 0; t < 4; ++t) {
            const __nv_bfloat16* g = gsrc[t];
            cp_async16(sb + t * TILE_BYTES + lr0 * 64 + sw0,
                       g + (size_t)lr0 * K + k0 + lc * 8);
            cp_async16(sb + t * TILE_BYTES + lr1 * 64 + sw1,
                       g + (size_t)lr1 * K + k0 + lc * 8);
        }
        cp_commit();
    };

    load_stage(0, 0);

    const int a_lrow   = (lane & 7) + ((lane >> 3) & 1) * 8;
    const int a_lchunk = lane >> 4;
    const int b_lrow   = lane & 7;
    const int b_lchunk = (lane >> 3) & 1;

    for (int ch = 0; ch < nch; ++ch) {
        if (ch + 1 < nch) {
            load_stage((ch + 1) & 1, (ch + 1) * 32);
            asm volatile("cp.async.wait_group 1;");
        } else {
            asm volatile("cp.async.wait_group 0;");
        }
        __syncthreads();

        const uint32_t sb = sbase + (uint32_t)(ch & 1) * STAGE_BYTES;

#pragma unroll
        for (int ks = 0; ks < 2; ++ks) {
            uint32_t afh[4][4], afl[4][4], bfh[4][2], bfl[4][2];
#pragma unroll
            for (int mt = 0; mt < 4; ++mt) {
                const int row = wm * 64 + mt * 16 + a_lrow;
                const int chn = 2 * ks + a_lchunk;
                const uint32_t addr = sb + (uint32_t)(row * 64)
                                    + (uint32_t)((chn ^ ((row >> 1) & 3)) << 4);
                ldmatrix_x4(afh[mt], addr);
                ldmatrix_x4(afl[mt], addr + TILE_BYTES);
            }
#pragma unroll
            for (int nt = 0; nt < 4; ++nt) {
                const int row = wn * 32 + nt * 8 + b_lrow;
                const int chn = 2 * ks + b_lchunk;
                const uint32_t addr = sb + 2 * TILE_BYTES + (uint32_t)(row * 64)
                                    + (uint32_t)((chn ^ ((row >> 1) & 3)) << 4);
                ldmatrix_x2(bfh[nt], addr);
                ldmatrix_x2(bfl[nt], addr + TILE_BYTES);
            }
#pragma unroll
            for (int mt = 0; mt < 4; ++mt)
#pragma unroll
                for (int nt = 0; nt < 4; ++nt) {
                    mma_bf16(acc[mt][nt], afh[mt], bfh[nt]);
                    mma_bf16(acc[mt][nt], afh[mt], bfl[nt]);
                    mma_bf16(acc[mt][nt], afl[mt], bfh[nt]);
                }
        }
        __syncthreads();
    }

    const int erow = lane >> 2;
    const int ecol = (lane & 3) * 2;
#pragma unroll
    for (int mt = 0; mt < 4; ++mt) {
#pragma unroll
        for (int nt = 0; nt < 4; ++nt) {
            const int col = ccol + wn * 32 + nt * 8 + ecol;
            const float b0 = bias[col], b1 = bias[col + 1];
            const int r0 = crow + wm * 64 + mt * 16 + erow;
            float2* p0 = reinterpret_cast<float2*>(Cout + (size_t)r0 * N + col);
            *p0 = make_float2(acc[mt][nt][0] + b0, acc[mt][nt][1] + b1);
            float2* p1 = reinterpret_cast<float2*>(Cout + (size_t)(r0 + 8) * N + col);
            *p1 = make_float2(acc[mt][nt][2] + b0, acc[mt][nt][3] + b1);
        }
    }
}

// ---------------------------------------------------------------------------
// qk_prep: fused RoPE + scale (q) + bf16 hi/lo split into padded [bh][n][128]
// ---------------------------------------------------------------------------
__global__ void qk_prep_kernel(const int* __restrict__ coords,
                               const float* __restrict__ qkv,
                               __nv_bfloat16* __restrict__ Qh, __nv_bfloat16* __restrict__ Ql,
                               __nv_bfloat16* __restrict__ Kh, __nv_bfloat16* __restrict__ Kl) {
    const int token = blockIdx.x;
    const int tid = threadIdx.x;   // 128
    __shared__ float cs[DD], sn[DD];

    const int c0 = coords[token * 3 + 0];
    const int c1 = coords[token * 3 + 1];
    const int c2 = coords[token * 3 + 2];
    if (tid < DD) {
        const int j = tid;
        int jj, dd, coord;
        if (j < 34)      { const int u = j;      jj = (u < 17) ? u : u - 17; dd = 34; coord = c0; }
        else if (j < 68) { const int u = j - 34; jj = (u < 17) ? u : u - 17; dd = 34; coord = c1; }
        else             { const int u = j - 68; jj = (u < 18) ? u : u - 18; dd = 36; coord = c2; }
        const float inv = powf(10000.0f, -(2.0f * (float)jj) / (float)dd);
        const float ang = (float)coord * inv;
        cs[j] = cosf(ang);
        sn[j] = sinf(ang);
    }
    __syncthreads();

    const int b = token >> 11, n = token & (NN - 1);
    const float scale = rsqrtf((float)DD);
    const float* base = qkv + (size_t)token * C3;

    for (int h = 0; h < HH; ++h) {
        const size_t o = ((size_t)(b * HH + h) * NN + n) * 128 + tid;
        if (tid < DD) {
            const int j = tid;
            const float qa = base[h * DD + j];
            const float qrot = (j < 52) ? -base[h * DD + j + 52] : base[h * DD + j - 52];
            const float qv = (qa * cs[j] + qrot * sn[j]) * scale;
            const __nv_bfloat16 qhv = __float2bfloat16(qv);
            Qh[o] = qhv;
            Ql[o] = __float2bfloat16(qv - __bfloat162float(qhv));

            const float ka = base[CC + h * DD + j];
            const float krot = (j < 52) ? -base[CC + h * DD + j + 52] : base[CC + h * DD + j - 52];
            const float kv = ka * cs[j] + krot * sn[j];
            const __nv_bfloat16 khv = __float2bfloat16(kv);
            Kh[o] = khv;
            Kl[o] = __float2bfloat16(kv - __bfloat162float(khv));
        } else {
            const __nv_bfloat16 z = __float2bfloat16(0.0f);
            Qh[o] = z; Ql[o] = z; Kh[o] = z; Kl[o] = z;
        }
    }
}

// ---------------------------------------------------------------------------
// vt_prep: V [token][h][d] fp32 -> Vt [bh][d][n] bf16 hi/lo (transpose)
// ---------------------------------------------------------------------------
__global__ void vt_prep_kernel(const float* __restrict__ qkv,
                               __nv_bfloat16* __restrict__ Vth,
                               __nv_bfloat16* __restrict__ Vtl) {
    __shared__ float t[32][33];
    const int bh = blockIdx.z;
    const int b = bh >> 4, h = bh & 15;
    const int n0 = blockIdx.x * 32;
    const int d0 = blockIdx.y * 32;
    const int tx = threadIdx.x, ty = threadIdx.y;
#pragma unroll
    for (int j = 0; j < 4; ++j) {
        const int d = d0 + tx, n = n0 + ty + 8 * j;
        if (d < DD)
            t[ty + 8 * j][tx] = qkv[(size_t)(b * NN + n) * C3 + 2 * CC + h * DD + d];
    }
    __syncthreads();
#pragma unroll
    for (int j = 0; j < 4; ++j) {
        const int d = d0 + ty + 8 * j, n = n0 + tx;
        if (d < DD) {
            const float v = t[tx][ty + 8 * j];
            const __nv_bfloat16 hv = __float2bfloat16(v);
            const size_t o = ((size_t)bh * DD + d) * NN + n;
            Vth[o] = hv;
            Vtl[o] = __float2bfloat16(v - __bfloat162float(hv));
        }
    }
}

// ---------------------------------------------------------------------------
// Flash attention on mma.sync bf16 hi/lo.
// CTA: 128 queries x 1 head. 8 warps x 16 rows. TK=64, double-buffered cp.async.
// Q/K smem rows: 256B (16 chunks of 16B), data chunks 0..13, swizzle c^(row&7).
// V smem rows: 128B (8 chunks), swizzle c^(row&7).
// ---------------------------------------------------------------------------
#define AT_STAGE 59392
#define AT_KL 16384
#define AT_V 32768
#define AT_VL 46080

__global__ __launch_bounds__(256, 1)
void attn_mma_kernel(const __nv_bfloat16* __restrict__ Qh, const __nv_bfloat16* __restrict__ Ql,
                     const __nv_bfloat16* __restrict__ Kh, const __nv_bfloat16* __restrict__ Kl,
                     const __nv_bfloat16* __restrict__ Vth, const __nv_bfloat16* __restrict__ Vtl,
                     __nv_bfloat16* __restrict__ Oh, __nv_bfloat16* __restrict__ Ol) {
    extern __shared__ char smem[];
    const uint32_t sb = smem_u32(smem);
    const int tid = threadIdx.x, lane = tid & 31, wid = tid >> 5;
    const int qt = blockIdx.x, h = blockIdx.y, b = blockIdx.z;
    const int bh = b * HH + h;

    const __nv_bfloat16* qh_p = Qh + ((size_t)bh * NN + qt * 128) * 128;
    const __nv_bfloat16* ql_p = Ql + ((size_t)bh * NN + qt * 128) * 128;
    const __nv_bfloat16* kh_p = Kh + (size_t)bh * NN * 128;
    const __nv_bfloat16* kl_p = Kl + (size_t)bh * NN * 128;
    const __nv_bfloat16* vh_p = Vth + (size_t)bh * DD * NN;
    const __nv_bfloat16* vl_p = Vtl + (size_t)bh * DD * NN;

    // ---- stage Q (14 data chunks per 256B row), extract a-frags ----
    for (int i = tid; i < 128 * 14; i += 256) {
        const int row = i / 14, c = i % 14;
        const uint32_t off = row * 256 + ((c ^ (row & 7)) << 4);
        cp_async16(sb + off, qh_p + row * 128 + c * 8);
        cp_async16(sb + AT_STAGE + off, ql_p + row * 128 + c * 8);
    }
    cp_commit();
    asm volatile("cp.async.wait_group 0;");
    __syncthreads();

    uint32_t qah[7][4], qal[7][4];
    {
        const int arow = wid * 16 + (lane & 7) + ((lane >> 3) & 1) * 8;
#pragma unroll
        for (int j = 0; j < 7; ++j) {
            const int chn = 2 * j + (lane >> 4);
            const uint32_t addr = sb + arow * 256 + ((chn ^ (arow & 7)) << 4);
            ldmatrix_x4(qah[j], addr);
            ldmatrix_x4(qal[j], addr + AT_STAGE);
        }
    }
    __syncthreads();

    float oc[13][4];
#pragma unroll
    for (int i = 0; i < 13; ++i) { oc[i][0] = oc[i][1] = oc[i][2] = oc[i][3] = 0.0f; }
    float m0 = -1e30f, m1 = -1e30f, l0 = 0.0f, l1 = 0.0f;

    auto load_stage = [&](int s, int kt) {
        const uint32_t st = sb + (uint32_t)s * AT_STAGE;
        const __nv_bfloat16* kh_t = kh_p + (size_t)kt * 64 * 128;
        const __nv_bfloat16* kl_t = kl_p + (size_t)kt * 64 * 128;
        for (int i = tid; i < 64 * 14; i += 256) {
            const int row = i / 14, c = i % 14;
            const uint32_t off = row * 256 + ((c ^ (row & 7)) << 4);
            cp_async16(st + off, kh_t + row * 128 + c * 8);
            cp_async16(st + AT_KL + off, kl_t + row * 128 + c * 8);
        }
        const __nv_bfloat16* vh_t = vh_p + kt * 64;
        const __nv_bfloat16* vl_t = vl_p + kt * 64;
        for (int i = tid; i < 832; i += 256) {
            const int row = i >> 3, c = i & 7;
            const uint32_t off = row * 128 + ((c ^ (row & 7)) << 4);
            cp_async16(st + AT_V + off, vh_t + (size_t)row * NN + c * 8);
            cp_async16(st + AT_VL + off, vl_t + (size_t)row * NN + c * 8);
        }
        cp_commit();
    };

    load_stage(0, 0);

    for (int kt = 0; kt < NN / 64; ++kt) {
        if (kt + 1 < NN / 64) {
            load_stage((kt + 1) & 1, kt + 1);
            asm volatile("cp.async.wait_group 1;");
        } else {
            asm volatile("cp.async.wait_group 0;");
        }
        __syncthreads();
        const uint32_t st = sb + (uint32_t)(kt & 1) * AT_STAGE;

        // ---- S = Q K^T (scale pre-folded into Q) ----
        float sc[8][4];
#pragma unroll
        for (int nt = 0; nt < 8; ++nt) { sc[nt][0] = sc[nt][1] = sc[nt][2] = sc[nt][3] = 0.0f; }

#pragma unroll
        for (int jp = 0; jp < 3; ++jp) {
#pragma unroll
            for (int nt = 0; nt < 8; ++nt) {
                const int brow = nt * 8 + (lane & 7);
                const int bchn = 4 * jp + (lane >> 3);
                const uint32_t addr = st + brow * 256 + ((bchn ^ (brow & 7)) << 4);
                uint32_t bh4[4], bl4[4];
                ldmatrix_x4(bh4, addr);
                ldmatrix_x4(bl4, addr + AT_KL);
                mma_bf16(sc[nt], qah[2 * jp], &bh4[0]);
                mma_bf16(sc[nt], qah[2 * jp], &bl4[0]);
                mma_bf16(sc[nt], qal[2 * jp], &bh4[0]);
                mma_bf16(sc[nt], qah[2 * jp + 1], &bh4[2]);
                mma_bf16(sc[nt], qah[2 * jp + 1], &bl4[2]);
                mma_bf16(sc[nt], qal[2 * jp + 1], &bh4[2]);
            }
        }
#pragma unroll
        for (int nt = 0; nt < 8; ++nt) {   // kstep j=6 (dims 96..111)
            const int brow = nt * 8 + (lane & 7);
            const int bchn = 12 + ((lane >> 3) & 1);
            const uint32_t addr = st + brow * 256 + ((bchn ^ (brow & 7)) << 4);
            uint32_t bh2[2], bl2[2];
            ldmatrix_x2(bh2, addr);
            ldmatrix_x2(bl2, addr + AT_KL);
            mma_bf16(sc[nt], qah[6], bh2);
            mma_bf16(sc[nt], qah[6], bl2);
            mma_bf16(sc[nt], qal[6], bh2);
        }

        // ---- online softmax ----
        float mx0 = m0, mx1 = m1;
#pragma unroll
        for (int nt = 0; nt < 8; ++nt) {
            mx0 = fmaxf(mx0, fmaxf(sc[nt][0], sc[nt][1]));
            mx1 = fmaxf(mx1, fmaxf(sc[nt][2], sc[nt][3]));
        }
        mx0 = fmaxf(mx0, __shfl_xor_sync(0xffffffffu, mx0, 1));
        mx0 = fmaxf(mx0, __shfl_xor_sync(0xffffffffu, mx0, 2));
        mx1 = fmaxf(mx1, __shfl_xor_sync(0xffffffffu, mx1, 1));
        mx1 = fmaxf(mx1, __shfl_xor_sync(0xffffffffu, mx1, 2));
        const float a0 = __expf(m0 - mx0), a1 = __expf(m1 - mx1);
        m0 = mx0; m1 = mx1;
        l0 *= a0; l1 *= a1;
#pragma unroll
        for (int i = 0; i < 13; ++i) {
            oc[i][0] *= a0; oc[i][1] *= a0; oc[i][2] *= a1; oc[i][3] *= a1;
        }

        uint32_t pah[4][4], pal[4][4];
#pragma unroll
        for (int jp = 0; jp < 4; ++jp) {
            const float p00 = __expf(sc[2 * jp][0] - mx0);
            const float p01 = __expf(sc[2 * jp][1] - mx0);
            const float p02 = __expf(sc[2 * jp][2] - mx1);
            const float p03 = __expf(sc[2 * jp][3] - mx1);
            const float p10 = __expf(sc[2 * jp + 1][0] - mx0);
            const float p11 = __expf(sc[2 * jp + 1][1] - mx0);
            const float p12 = __expf(sc[2 * jp + 1][2] - mx1);
            const float p13 = __expf(sc[2 * jp + 1][3] - mx1);
            l0 += p00 + p01 + p10 + p11;
            l1 += p02 + p03 + p12 + p13;
            pack_hilo(p00, p01, pah[jp][0], pal[jp][0]);
            pack_hilo(p02, p03, pah[jp][1], pal[jp][1]);
            pack_hilo(p10, p11, pah[jp][2], pal[jp][2]);
            pack_hilo(p12, p13, pah[jp][3], pal[jp][3]);
        }

        // ---- O += P V ----
#pragma unroll
        for (int jph = 0; jph < 2; ++jph) {
#pragma unroll
            for (int ntd = 0; ntd < 13; ++ntd) {
                const int vrow = ntd * 8 + (lane & 7);
                const int vchn = 4 * jph + (lane >> 3);
                const uint32_t addr = st + AT_V + vrow * 128 + ((vchn ^ (vrow & 7)) << 4);
                uint32_t vh4[4], vl4[4];
                ldmatrix_x4(vh4, addr);
                ldmatrix_x4(vl4, addr + (AT_VL - AT_V));
                mma_bf16(oc[ntd], pah[2 * jph], &vh4[0]);
                mma_bf16(oc[ntd], pah[2 * jph], &vl4[0]);
                mma_bf16(oc[ntd], pal[2 * jph], &vh4[0]);
                mma_bf16(oc[ntd], pah[2 * jph + 1], &vh4[2]);
                mma_bf16(oc[ntd], pah[2 * jph + 1], &vl4[2]);
                mma_bf16(oc[ntd], pal[2 * jph + 1], &vh4[2]);
            }
        }
        __syncthreads();
    }

    // ---- epilogue: normalize, split hi/lo, write proj-GEMM inputs ----
    l0 += __shfl_xor_sync(0xffffffffu, l0, 1);
    l0 += __shfl_xor_sync(0xffffffffu, l0, 2);
    l1 += __shfl_xor_sync(0xffffffffu, l1, 1);
    l1 += __shfl_xor_sync(0xffffffffu, l1, 2);
    const float inv0 = 1.0f / l0, inv1 = 1.0f / l1;
    const int row0 = qt * 128 + wid * 16 + (lane >> 2);
    const size_t tok0 = (size_t)b * NN + row0;
    const int colbase = h * DD + 2 * (lane & 3);
#pragma unroll
    for (int ntd = 0; ntd < 13; ++ntd) {
        const int col = colbase + ntd * 8;
        uint32_t hi, lo;
        pack_hilo(oc[ntd][0] * inv0, oc[ntd][1] * inv0, hi, lo);
        *reinterpret_cast<uint32_t*>(Oh + tok0 * CC + col) = hi;
        *reinterpret_cast<uint32_t*>(Ol + tok0 * CC + col) = lo;
        pack_hilo(oc[ntd][2] * inv1, oc[ntd][3] * inv1, hi, lo);
        *reinterpret_cast<uint32_t*>(Oh + (tok0 + 8) * CC + col) = hi;
        *reinterpret_cast<uint32_t*>(Ol + (tok0 + 8) * CC + col) = lo;
    }
}

// ---------------------------------------------------------------------------
// Launch
// ---------------------------------------------------------------------------
extern "C" void kernel_launch(void* const* d_in, const int* in_sizes, int n_in,
                              void* d_out, int out_size) {
    const float* x = nullptr;
    const int*   coords = nullptr;
    const float* qkv_w = nullptr;
    const float* qkv_b = nullptr;
    const float* proj_w = nullptr;
    const float* proj_b = nullptr;
    for (int i = 0; i < n_in; ++i) {
        switch (in_sizes[i]) {
            case TOKENS * CC:      x      = (const float*)d_in[i]; break;
            case TOKENS * 3:       coords = (const int*)d_in[i];   break;
            case CC * C3:          qkv_w  = (const float*)d_in[i]; break;
            case C3:               qkv_b  = (const float*)d_in[i]; break;
            case CC * CC:          proj_w = (const float*)d_in[i]; break;
            case CC:               proj_b = (const float*)d_in[i]; break;
            default: break;
        }
    }
    float* out = (float*)d_out;

    float* qkv;
    __nv_bfloat16 *xh, *xl, *ah, *al, *wqh, *wql, *wph, *wpl;
    __nv_bfloat16 *qh, *ql, *kh, *kl, *vth, *vtl;
    cudaGetSymbolAddress((void**)&qkv, g_qkv);
    cudaGetSymbolAddress((void**)&xh,  g_xh);
    cudaGetSymbolAddress((void**)&xl,  g_xl);
    cudaGetSymbolAddress((void**)&ah,  g_ah);
    cudaGetSymbolAddress((void**)&al,  g_al);
    cudaGetSymbolAddress((void**)&wqh, g_wqh);
    cudaGetSymbolAddress((void**)&wql, g_wql);
    cudaGetSymbolAddress((void**)&wph, g_wph);
    cudaGetSymbolAddress((void**)&wpl, g_wpl);
    cudaGetSymbolAddress((void**)&qh,  g_qh);
    cudaGetSymbolAddress((void**)&ql,  g_ql);
    cudaGetSymbolAddress((void**)&kh,  g_kh);
    cudaGetSymbolAddress((void**)&kl,  g_kl);
    cudaGetSymbolAddress((void**)&vth, g_vth);
    cudaGetSymbolAddress((void**)&vtl, g_vtl);

    const int gemm_smem = 2 * STAGE_BYTES;
    cudaFuncSetAttribute(mma_gemm_kernel, cudaFuncAttributeMaxDynamicSharedMemorySize, gemm_smem);
    const int attn_smem = 2 * AT_STAGE;  // 118784
    cudaFuncSetAttribute(attn_mma_kernel, cudaFuncAttributeMaxDynamicSharedMemorySize, attn_smem);

    // 1) split x
    convert_split_kernel<<<4096, 256>>>(x, xh, xl, TOKENS * CC);

    // 2) transpose+split qkv_w
    {
        dim3 grid(C3 / 32, CC / 32);
        transpose_split_kernel<<<grid, dim3(32, 8)>>>(qkv_w, wqh, wql, CC, C3);
    }

    // 3) QKV GEMM
    {
        dim3 grid(C3 / 128, TOKENS / 128);
        mma_gemm_kernel<<<grid, 256, gemm_smem>>>(xh, xl, wqh, wql, qkv_b, qkv,
                                                  TOKENS, C3, CC);
    }

    // 4) RoPE + scale + split q/k; transpose+split v
    qk_prep_kernel<<<TOKENS, 128>>>(coords, qkv, qh, ql, kh, kl);
    {
        dim3 grid(NN / 32, (DD + 31) / 32, BB * HH);
        vt_prep_kernel<<<grid, dim3(32, 8)>>>(qkv, vth, vtl);
    }

    // 5) Flash attention on tensor cores -> writes proj inputs (ah/al)
    {
        dim3 grid(NN / 128, HH, BB);
        attn_mma_kernel<<<grid, 256, attn_smem>>>(qh, ql, kh, kl, vth, vtl, ah, al);
    }

    // 6) transpose+split proj_w
    {
        dim3 grid(CC / 32, CC / 32);
        transpose_split_kernel<<<grid, dim3(32, 8)>>>(proj_w, wph, wpl, CC, CC);
    }

    // 7) Projection GEMM
    {
        dim3 grid(CC / 128, TOKENS / 128);
        mma_gemm_kernel<<<grid, 256, gemm_smem>>>(ah, al, wph, wpl, proj_b, out,
                                                  TOKENS, CC, CC);
    }
}

// round 6
// speedup vs baseline: 4.4624x; 1.0834x over previous
#include <cuda_runtime.h>
#include <cuda_bf16.h>
#include <math.h>
#include <stdint.h>

// Problem constants
#define BB 2
#define NN 2048
#define CC 1664
#define HH 16
#define DD 104
#define C3 (3 * CC)          // 4992
#define TOKENS (BB * NN)     // 4096

// ---------------------------------------------------------------------------
// Scratch (no allocations allowed)
// ---------------------------------------------------------------------------
__device__ __align__(256) float g_qkv[(size_t)TOKENS * C3];
__device__ __align__(256) __nv_bfloat16 g_xh[(size_t)TOKENS * CC];
__device__ __align__(256) __nv_bfloat16 g_xl[(size_t)TOKENS * CC];
__device__ __align__(256) __nv_bfloat16 g_ah[(size_t)TOKENS * CC];
__device__ __align__(256) __nv_bfloat16 g_al[(size_t)TOKENS * CC];
__device__ __align__(256) __nv_bfloat16 g_wqh[(size_t)C3 * CC];
__device__ __align__(256) __nv_bfloat16 g_wql[(size_t)C3 * CC];
__device__ __align__(256) __nv_bfloat16 g_wph[(size_t)CC * CC];
__device__ __align__(256) __nv_bfloat16 g_wpl[(size_t)CC * CC];
// attention operand buffers: Q/K padded to 128 dims, V transposed [d][n]
__device__ __align__(256) __nv_bfloat16 g_qh[(size_t)BB * HH * NN * 128];
__device__ __align__(256) __nv_bfloat16 g_ql[(size_t)BB * HH * NN * 128];
__device__ __align__(256) __nv_bfloat16 g_kh[(size_t)BB * HH * NN * 128];
__device__ __align__(256) __nv_bfloat16 g_kl[(size_t)BB * HH * NN * 128];
__device__ __align__(256) __nv_bfloat16 g_vth[(size_t)BB * HH * DD * NN];
__device__ __align__(256) __nv_bfloat16 g_vtl[(size_t)BB * HH * DD * NN];

// ---------------------------------------------------------------------------
// Helpers
// ---------------------------------------------------------------------------
__device__ __forceinline__ uint32_t smem_u32(const void* p) {
    uint32_t a;
    asm("{ .reg .u64 t; cvta.to.shared.u64 t, %1; cvt.u32.u64 %0, t; }" : "=r"(a) : "l"(p));
    return a;
}
__device__ __forceinline__ void cp_async16(uint32_t dst, const void* src) {
    asm volatile("cp.async.cg.shared.global [%0], [%1], 16;" :: "r"(dst), "l"(src));
}
__device__ __forceinline__ void cp_commit() {
    asm volatile("cp.async.commit_group;");
}
__device__ __forceinline__ void ldmatrix_x4(uint32_t* r, uint32_t addr) {
    asm volatile("ldmatrix.sync.aligned.m8n8.x4.shared.b16 {%0,%1,%2,%3}, [%4];"
                 : "=r"(r[0]), "=r"(r[1]), "=r"(r[2]), "=r"(r[3]) : "r"(addr));
}
__device__ __forceinline__ void ldmatrix_x2(uint32_t* r, uint32_t addr) {
    asm volatile("ldmatrix.sync.aligned.m8n8.x2.shared.b16 {%0,%1}, [%2];"
                 : "=r"(r[0]), "=r"(r[1]) : "r"(addr));
}
__device__ __forceinline__ void mma_bf16(float* c, const uint32_t* a, const uint32_t* b) {
    asm volatile("mma.sync.aligned.m16n8k16.row.col.f32.bf16.bf16.f32 "
                 "{%0,%1,%2,%3}, {%4,%5,%6,%7}, {%8,%9}, {%0,%1,%2,%3};"
                 : "+f"(c[0]), "+f"(c[1]), "+f"(c[2]), "+f"(c[3])
                 : "r"(a[0]), "r"(a[1]), "r"(a[2]), "r"(a[3]), "r"(b[0]), "r"(b[1]));
}
__device__ __forceinline__ void pack_hilo(float a, float b, uint32_t& hi, uint32_t& lo) {
    const __nv_bfloat16 ha = __float2bfloat16(a);
    const __nv_bfloat16 hb = __float2bfloat16(b);
    const __nv_bfloat16 la = __float2bfloat16(a - __bfloat162float(ha));
    const __nv_bfloat16 lb = __float2bfloat16(b - __bfloat162float(hb));
    hi = (uint32_t)*reinterpret_cast<const uint16_t*>(&ha) |
         ((uint32_t)*reinterpret_cast<const uint16_t*>(&hb) << 16);
    lo = (uint32_t)*reinterpret_cast<const uint16_t*>(&la) |
         ((uint32_t)*reinterpret_cast<const uint16_t*>(&lb) << 16);
}
__device__ __forceinline__ uint32_t pack_hi(float a, float b) {
    const __nv_bfloat16 ha = __float2bfloat16(a);
    const __nv_bfloat16 hb = __float2bfloat16(b);
    return (uint32_t)*reinterpret_cast<const uint16_t*>(&ha) |
           ((uint32_t)*reinterpret_cast<const uint16_t*>(&hb) << 16);
}

// ---------------------------------------------------------------------------
// fp32 -> bf16 hi/lo split
// ---------------------------------------------------------------------------
__global__ void convert_split_kernel(const float* __restrict__ src,
                                     __nv_bfloat16* __restrict__ hi,
                                     __nv_bfloat16* __restrict__ lo, int n) {
    for (int i = blockIdx.x * blockDim.x + threadIdx.x; i < n; i += gridDim.x * blockDim.x) {
        const float v = src[i];
        const __nv_bfloat16 h = __float2bfloat16(v);
        hi[i] = h;
        lo[i] = __float2bfloat16(v - __bfloat162float(h));
    }
}

// ---------------------------------------------------------------------------
// W[Kr][Nc] row-major  ->  T[Nc][Kr] bf16 hi/lo
// ---------------------------------------------------------------------------
__global__ void transpose_split_kernel(const float* __restrict__ W,
                                       __nv_bfloat16* __restrict__ Th,
                                       __nv_bfloat16* __restrict__ Tl,
                                       int Kr, int Nc) {
    __shared__ float t[32][33];
    const int x = blockIdx.x * 32 + threadIdx.x;
    const int y0 = blockIdx.y * 32;
    for (int j = threadIdx.y; j < 32; j += 8)
        t[j][threadIdx.x] = W[(size_t)(y0 + j) * Nc + x];
    __syncthreads();
    const int ox = y0 + threadIdx.x;
    const int oy0 = blockIdx.x * 32;
    for (int j = threadIdx.y; j < 32; j += 8) {
        const float v = t[threadIdx.x][j];
        const __nv_bfloat16 h = __float2bfloat16(v);
        Th[(size_t)(oy0 + j) * Kr + ox] = h;
        Tl[(size_t)(oy0 + j) * Kr + ox] = __float2bfloat16(v - __bfloat162float(h));
    }
}

// ---------------------------------------------------------------------------
// mma.sync GEMM: 3-stage cp.async pipeline, one sync per chunk.
// ---------------------------------------------------------------------------
#define TILE_BYTES 8192
#define STAGE_BYTES 32768

__global__ __launch_bounds__(256, 1)
void mma_gemm_kernel(const __nv_bfloat16* __restrict__ Ah,
                     const __nv_bfloat16* __restrict__ Al,
                     const __nv_bfloat16* __restrict__ Bh,
                     const __nv_bfloat16* __restrict__ Bl,
                     const float* __restrict__ bias,
                     float* __restrict__ Cout,
                     int M, int N, int K) {
    extern __shared__ char smem[];
    const uint32_t sbase = smem_u32(smem);
    const int tid  = threadIdx.x;
    const int lane = tid & 31;
    const int wid  = tid >> 5;
    const int wm   = wid & 1;
    const int wn   = wid >> 1;
    const int crow = blockIdx.y * 128;
    const int ccol = blockIdx.x * 128;

    const __nv_bfloat16* gsrc[4];
    gsrc[0] = Ah + (size_t)crow * K;
    gsrc[1] = Al + (size_t)crow * K;
    gsrc[2] = Bh + (size_t)ccol * K;
    gsrc[3] = Bl + (size_t)ccol * K;

    const int lc  = tid & 3;
    const int lr0 = tid >> 2;
    const int lr1 = lr0 + 64;
    const uint32_t sw0 = (uint32_t)((lc ^ ((lr0 >> 1) & 3)) << 4);
    const uint32_t sw1 = (uint32_t)((lc ^ ((lr1 >> 1) & 3)) << 4);

    float acc[4][4][4];
#pragma unroll
    for (int mt = 0; mt < 4; ++mt)
#pragma unroll
        for (int nt = 0; nt < 4; ++nt)
#pragma unroll
            for (int j = 0; j < 4; ++j) acc[mt][nt][j] = 0.0f;

    const int nch = K / 32;

    auto load_stage = [&](int stage, int k0) {
        const uint32_t sb = sbase + (uint32_t)stage * STAGE_BYTES;
#pragma unroll
        for (int t = 0; t < 4; ++t) {
            const __nv_bfloat16* g = gsrc[t];
            cp_async16(sb + t * TILE_BYTES + lr0 * 64 + sw0,
                       g + (size_t)lr0 * K + k0 + lc * 8);
            cp_async16(sb + t * TILE_BYTES + lr1 * 64 + sw1,
                       g + (size_t)lr1 * K + k0 + lc * 8);
        }
        cp_commit();
    };

    load_stage(0, 0);
    load_stage(1, 32);

    const int a_lrow   = (lane & 7) + ((lane >> 3) & 1) * 8;
    const int a_lchunk = lane >> 4;
    const int b_lrow   = lane & 7;
    const int b_lchunk = (lane >> 3) & 1;

    for (int ch = 0; ch < nch; ++ch) {
        if (ch + 2 <= nch) {
            asm volatile("cp.async.wait_group 1;");
        } else {
            asm volatile("cp.async.wait_group 0;");
        }
        __syncthreads();
        if (ch + 2 < nch) load_stage((ch + 2) % 3, (ch + 2) * 32);

        const uint32_t sb = sbase + (uint32_t)(ch % 3) * STAGE_BYTES;

#pragma unroll
        for (int ks = 0; ks < 2; ++ks) {
            uint32_t afh[4][4], afl[4][4], bfh[4][2], bfl[4][2];
#pragma unroll
            for (int mt = 0; mt < 4; ++mt) {
                const int row = wm * 64 + mt * 16 + a_lrow;
                const int chn = 2 * ks + a_lchunk;
                const uint32_t addr = sb + (uint32_t)(row * 64)
                                    + (uint32_t)((chn ^ ((row >> 1) & 3)) << 4);
                ldmatrix_x4(afh[mt], addr);
                ldmatrix_x4(afl[mt], addr + TILE_BYTES);
            }
#pragma unroll
            for (int nt = 0; nt < 4; ++nt) {
                const int row = wn * 32 + nt * 8 + b_lrow;
                const int chn = 2 * ks + b_lchunk;
                const uint32_t addr = sb + 2 * TILE_BYTES + (uint32_t)(row * 64)
                                    + (uint32_t)((chn ^ ((row >> 1) & 3)) << 4);
                ldmatrix_x2(bfh[nt], addr);
                ldmatrix_x2(bfl[nt], addr + TILE_BYTES);
            }
#pragma unroll
            for (int mt = 0; mt < 4; ++mt)
#pragma unroll
                for (int nt = 0; nt < 4; ++nt) {
                    mma_bf16(acc[mt][nt], afh[mt], bfh[nt]);
                    mma_bf16(acc[mt][nt], afh[mt], bfl[nt]);
                    mma_bf16(acc[mt][nt], afl[mt], bfh[nt]);
                }
        }
    }

    const int erow = lane >> 2;
    const int ecol = (lane & 3) * 2;
#pragma unroll
    for (int mt = 0; mt < 4; ++mt) {
#pragma unroll
        for (int nt = 0; nt < 4; ++nt) {
            const int col = ccol + wn * 32 + nt * 8 + ecol;
            const float b0 = bias[col], b1 = bias[col + 1];
            const int r0 = crow + wm * 64 + mt * 16 + erow;
            float2* p0 = reinterpret_cast<float2*>(Cout + (size_t)r0 * N + col);
            *p0 = make_float2(acc[mt][nt][0] + b0, acc[mt][nt][1] + b1);
            float2* p1 = reinterpret_cast<float2*>(Cout + (size_t)(r0 + 8) * N + col);
            *p1 = make_float2(acc[mt][nt][2] + b0, acc[mt][nt][3] + b1);
        }
    }
}

// ---------------------------------------------------------------------------
// qk_prep: fused RoPE + scale (q) + bf16 hi/lo split into padded [bh][n][128]
// ---------------------------------------------------------------------------
__global__ void qk_prep_kernel(const int* __restrict__ coords,
                               const float* __restrict__ qkv,
                               __nv_bfloat16* __restrict__ Qh, __nv_bfloat16* __restrict__ Ql,
                               __nv_bfloat16* __restrict__ Kh, __nv_bfloat16* __restrict__ Kl) {
    const int token = blockIdx.x;
    const int tid = threadIdx.x;   // 128
    __shared__ float cs[DD], sn[DD];

    const int c0 = coords[token * 3 + 0];
    const int c1 = coords[token * 3 + 1];
    const int c2 = coords[token * 3 + 2];
    if (tid < DD) {
        const int j = tid;
        int jj, dd, coord;
        if (j < 34)      { const int u = j;      jj = (u < 17) ? u : u - 17; dd = 34; coord = c0; }
        else if (j < 68) { const int u = j - 34; jj = (u < 17) ? u : u - 17; dd = 34; coord = c1; }
        else             { const int u = j - 68; jj = (u < 18) ? u : u - 18; dd = 36; coord = c2; }
        const float inv = powf(10000.0f, -(2.0f * (float)jj) / (float)dd);
        const float ang = (float)coord * inv;
        cs[j] = cosf(ang);
        sn[j] = sinf(ang);
    }
    __syncthreads();

    const int b = token >> 11, n = token & (NN - 1);
    const float scale = rsqrtf((float)DD);
    const float* base = qkv + (size_t)token * C3;

    for (int h = 0; h < HH; ++h) {
        const size_t o = ((size_t)(b * HH + h) * NN + n) * 128 + tid;
        if (tid < DD) {
            const int j = tid;
            const float qa = base[h * DD + j];
            const float qrot = (j < 52) ? -base[h * DD + j + 52] : base[h * DD + j - 52];
            const float qv = (qa * cs[j] + qrot * sn[j]) * scale;
            const __nv_bfloat16 qhv = __float2bfloat16(qv);
            Qh[o] = qhv;
            Ql[o] = __float2bfloat16(qv - __bfloat162float(qhv));

            const float ka = base[CC + h * DD + j];
            const float krot = (j < 52) ? -base[CC + h * DD + j + 52] : base[CC + h * DD + j - 52];
            const float kv = ka * cs[j] + krot * sn[j];
            const __nv_bfloat16 khv = __float2bfloat16(kv);
            Kh[o] = khv;
            Kl[o] = __float2bfloat16(kv - __bfloat162float(khv));
        } else {
            const __nv_bfloat16 z = __float2bfloat16(0.0f);
            Qh[o] = z; Ql[o] = z; Kh[o] = z; Kl[o] = z;
        }
    }
}

// ---------------------------------------------------------------------------
// vt_prep: V [token][h][d] fp32 -> Vt [bh][d][n] bf16 hi/lo (transpose)
// ---------------------------------------------------------------------------
__global__ void vt_prep_kernel(const float* __restrict__ qkv,
                               __nv_bfloat16* __restrict__ Vth,
                               __nv_bfloat16* __restrict__ Vtl) {
    __shared__ float t[32][33];
    const int bh = blockIdx.z;
    const int b = bh >> 4, h = bh & 15;
    const int n0 = blockIdx.x * 32;
    const int d0 = blockIdx.y * 32;
    const int tx = threadIdx.x, ty = threadIdx.y;
#pragma unroll
    for (int j = 0; j < 4; ++j) {
        const int d = d0 + tx, n = n0 + ty + 8 * j;
        if (d < DD)
            t[ty + 8 * j][tx] = qkv[(size_t)(b * NN + n) * C3 + 2 * CC + h * DD + d];
    }
    __syncthreads();
#pragma unroll
    for (int j = 0; j < 4; ++j) {
        const int d = d0 + ty + 8 * j, n = n0 + tx;
        if (d < DD) {
            const float v = t[tx][ty + 8 * j];
            const __nv_bfloat16 hv = __float2bfloat16(v);
            const size_t o = ((size_t)bh * DD + d) * NN + n;
            Vth[o] = hv;
            Vtl[o] = __float2bfloat16(v - __bfloat162float(hv));
        }
    }
}

// ---------------------------------------------------------------------------
// Flash attention on mma.sync bf16 hi/lo. 3-stage pipeline, one sync per tile.
// P uses hi-only against Vh (Pl*Vh dropped; Ph*Vl kept for V quantization).
// ---------------------------------------------------------------------------
#define AT_STAGE 59392
#define AT_KL 16384
#define AT_V 32768
#define AT_VL 46080

__global__ __launch_bounds__(256, 1)
void attn_mma_kernel(const __nv_bfloat16* __restrict__ Qh, const __nv_bfloat16* __restrict__ Ql,
                     const __nv_bfloat16* __restrict__ Kh, const __nv_bfloat16* __restrict__ Kl,
                     const __nv_bfloat16* __restrict__ Vth, const __nv_bfloat16* __restrict__ Vtl,
                     __nv_bfloat16* __restrict__ Oh, __nv_bfloat16* __restrict__ Ol) {
    extern __shared__ char smem[];
    const uint32_t sb = smem_u32(smem);
    const int tid = threadIdx.x, lane = tid & 31, wid = tid >> 5;
    const int qt = blockIdx.x, h = blockIdx.y, b = blockIdx.z;
    const int bh = b * HH + h;

    const __nv_bfloat16* qh_p = Qh + ((size_t)bh * NN + qt * 128) * 128;
    const __nv_bfloat16* ql_p = Ql + ((size_t)bh * NN + qt * 128) * 128;
    const __nv_bfloat16* kh_p = Kh + (size_t)bh * NN * 128;
    const __nv_bfloat16* kl_p = Kl + (size_t)bh * NN * 128;
    const __nv_bfloat16* vh_p = Vth + (size_t)bh * DD * NN;
    const __nv_bfloat16* vl_p = Vtl + (size_t)bh * DD * NN;

    // ---- stage Q (14 data chunks per 256B row), extract a-frags ----
    for (int i = tid; i < 128 * 14; i += 256) {
        const int row = i / 14, c = i % 14;
        const uint32_t off = row * 256 + ((c ^ (row & 7)) << 4);
        cp_async16(sb + off, qh_p + row * 128 + c * 8);
        cp_async16(sb + AT_STAGE + off, ql_p + row * 128 + c * 8);
    }
    cp_commit();
    asm volatile("cp.async.wait_group 0;");
    __syncthreads();

    uint32_t qah[7][4], qal[7][4];
    {
        const int arow = wid * 16 + (lane & 7) + ((lane >> 3) & 1) * 8;
#pragma unroll
        for (int j = 0; j < 7; ++j) {
            const int chn = 2 * j + (lane >> 4);
            const uint32_t addr = sb + arow * 256 + ((chn ^ (arow & 7)) << 4);
            ldmatrix_x4(qah[j], addr);
            ldmatrix_x4(qal[j], addr + AT_STAGE);
        }
    }
    __syncthreads();

    float oc[13][4];
#pragma unroll
    for (int i = 0; i < 13; ++i) { oc[i][0] = oc[i][1] = oc[i][2] = oc[i][3] = 0.0f; }
    float m0 = -1e30f, m1 = -1e30f, l0 = 0.0f, l1 = 0.0f;

    auto load_stage = [&](int s, int kt) {
        const uint32_t st = sb + (uint32_t)s * AT_STAGE;
        const __nv_bfloat16* kh_t = kh_p + (size_t)kt * 64 * 128;
        const __nv_bfloat16* kl_t = kl_p + (size_t)kt * 64 * 128;
        for (int i = tid; i < 64 * 14; i += 256) {
            const int row = i / 14, c = i % 14;
            const uint32_t off = row * 256 + ((c ^ (row & 7)) << 4);
            cp_async16(st + off, kh_t + row * 128 + c * 8);
            cp_async16(st + AT_KL + off, kl_t + row * 128 + c * 8);
        }
        const __nv_bfloat16* vh_t = vh_p + kt * 64;
        const __nv_bfloat16* vl_t = vl_p + kt * 64;
        for (int i = tid; i < 832; i += 256) {
            const int row = i >> 3, c = i & 7;
            const uint32_t off = row * 128 + ((c ^ (row & 7)) << 4);
            cp_async16(st + AT_V + off, vh_t + (size_t)row * NN + c * 8);
            cp_async16(st + AT_VL + off, vl_t + (size_t)row * NN + c * 8);
        }
        cp_commit();
    };

    const int nkt = NN / 64;
    load_stage(0, 0);
    load_stage(1, 1);

    for (int kt = 0; kt < nkt; ++kt) {
        if (kt + 2 <= nkt) {
            asm volatile("cp.async.wait_group 1;");
        } else {
            asm volatile("cp.async.wait_group 0;");
        }
        __syncthreads();
        if (kt + 2 < nkt) load_stage((kt + 2) % 3, kt + 2);

        const uint32_t st = sb + (uint32_t)(kt % 3) * AT_STAGE;

        // ---- S = Q K^T (scale pre-folded into Q) ----
        float sc[8][4];
#pragma unroll
        for (int nt = 0; nt < 8; ++nt) { sc[nt][0] = sc[nt][1] = sc[nt][2] = sc[nt][3] = 0.0f; }

#pragma unroll
        for (int jp = 0; jp < 3; ++jp) {
#pragma unroll
            for (int nt = 0; nt < 8; ++nt) {
                const int brow = nt * 8 + (lane & 7);
                const int bchn = 4 * jp + (lane >> 3);
                const uint32_t addr = st + brow * 256 + ((bchn ^ (brow & 7)) << 4);
                uint32_t bh4[4], bl4[4];
                ldmatrix_x4(bh4, addr);
                ldmatrix_x4(bl4, addr + AT_KL);
                mma_bf16(sc[nt], qah[2 * jp], &bh4[0]);
                mma_bf16(sc[nt], qah[2 * jp], &bl4[0]);
                mma_bf16(sc[nt], qal[2 * jp], &bh4[0]);
                mma_bf16(sc[nt], qah[2 * jp + 1], &bh4[2]);
                mma_bf16(sc[nt], qah[2 * jp + 1], &bl4[2]);
                mma_bf16(sc[nt], qal[2 * jp + 1], &bh4[2]);
            }
        }
#pragma unroll
        for (int nt = 0; nt < 8; ++nt) {   // kstep j=6 (dims 96..111)
            const int brow = nt * 8 + (lane & 7);
            const int bchn = 12 + ((lane >> 3) & 1);
            const uint32_t addr = st + brow * 256 + ((bchn ^ (brow & 7)) << 4);
            uint32_t bh2[2], bl2[2];
            ldmatrix_x2(bh2, addr);
            ldmatrix_x2(bl2, addr + AT_KL);
            mma_bf16(sc[nt], qah[6], bh2);
            mma_bf16(sc[nt], qah[6], bl2);
            mma_bf16(sc[nt], qal[6], bh2);
        }

        // ---- online softmax ----
        float mx0 = m0, mx1 = m1;
#pragma unroll
        for (int nt = 0; nt < 8; ++nt) {
            mx0 = fmaxf(mx0, fmaxf(sc[nt][0], sc[nt][1]));
            mx1 = fmaxf(mx1, fmaxf(sc[nt][2], sc[nt][3]));
        }
        mx0 = fmaxf(mx0, __shfl_xor_sync(0xffffffffu, mx0, 1));
        mx0 = fmaxf(mx0, __shfl_xor_sync(0xffffffffu, mx0, 2));
        mx1 = fmaxf(mx1, __shfl_xor_sync(0xffffffffu, mx1, 1));
        mx1 = fmaxf(mx1, __shfl_xor_sync(0xffffffffu, mx1, 2));
        const float a0 = __expf(m0 - mx0), a1 = __expf(m1 - mx1);
        m0 = mx0; m1 = mx1;
        l0 *= a0; l1 *= a1;
#pragma unroll
        for (int i = 0; i < 13; ++i) {
            oc[i][0] *= a0; oc[i][1] *= a0; oc[i][2] *= a1; oc[i][3] *= a1;
        }

        uint32_t pah[4][4];
#pragma unroll
        for (int jp = 0; jp < 4; ++jp) {
            const float p00 = __expf(sc[2 * jp][0] - mx0);
            const float p01 = __expf(sc[2 * jp][1] - mx0);
            const float p02 = __expf(sc[2 * jp][2] - mx1);
            const float p03 = __expf(sc[2 * jp][3] - mx1);
            const float p10 = __expf(sc[2 * jp + 1][0] - mx0);
            const float p11 = __expf(sc[2 * jp + 1][1] - mx0);
            const float p12 = __expf(sc[2 * jp + 1][2] - mx1);
            const float p13 = __expf(sc[2 * jp + 1][3] - mx1);
            l0 += p00 + p01 + p10 + p11;
            l1 += p02 + p03 + p12 + p13;
            pah[jp][0] = pack_hi(p00, p01);
            pah[jp][1] = pack_hi(p02, p03);
            pah[jp][2] = pack_hi(p10, p11);
            pah[jp][3] = pack_hi(p12, p13);
        }

        // ---- O += P V (Ph*Vh + Ph*Vl) ----
#pragma unroll
        for (int jph = 0; jph < 2; ++jph) {
#pragma unroll
            for (int ntd = 0; ntd < 13; ++ntd) {
                const int vrow = ntd * 8 + (lane & 7);
                const int vchn = 4 * jph + (lane >> 3);
                const uint32_t addr = st + AT_V + vrow * 128 + ((vchn ^ (vrow & 7)) << 4);
                uint32_t vh4[4], vl4[4];
                ldmatrix_x4(vh4, addr);
                ldmatrix_x4(vl4, addr + (AT_VL - AT_V));
                mma_bf16(oc[ntd], pah[2 * jph], &vh4[0]);
                mma_bf16(oc[ntd], pah[2 * jph], &vl4[0]);
                mma_bf16(oc[ntd], pah[2 * jph + 1], &vh4[2]);
                mma_bf16(oc[ntd], pah[2 * jph + 1], &vl4[2]);
            }
        }
    }

    // ---- epilogue: normalize, split hi/lo, write proj-GEMM inputs ----
    l0 += __shfl_xor_sync(0xffffffffu, l0, 1);
    l0 += __shfl_xor_sync(0xffffffffu, l0, 2);
    l1 += __shfl_xor_sync(0xffffffffu, l1, 1);
    l1 += __shfl_xor_sync(0xffffffffu, l1, 2);
    const float inv0 = 1.0f / l0, inv1 = 1.0f / l1;
    const int row0 = qt * 128 + wid * 16 + (lane >> 2);
    const size_t tok0 = (size_t)b * NN + row0;
    const int colbase = h * DD + 2 * (lane & 3);
#pragma unroll
    for (int ntd = 0; ntd < 13; ++ntd) {
        const int col = colbase + ntd * 8;
        uint32_t hi, lo;
        pack_hilo(oc[ntd][0] * inv0, oc[ntd][1] * inv0, hi, lo);
        *reinterpret_cast<uint32_t*>(Oh + tok0 * CC + col) = hi;
        *reinterpret_cast<uint32_t*>(Ol + tok0 * CC + col) = lo;
        pack_hilo(oc[ntd][2] * inv1, oc[ntd][3] * inv1, hi, lo);
        *reinterpret_cast<uint32_t*>(Oh + (tok0 + 8) * CC + col) = hi;
        *reinterpret_cast<uint32_t*>(Ol + (tok0 + 8) * CC + col) = lo;
    }
}

// ---------------------------------------------------------------------------
// Launch
// ---------------------------------------------------------------------------
extern "C" void kernel_launch(void* const* d_in, const int* in_sizes, int n_in,
                              void* d_out, int out_size) {
    const float* x = nullptr;
    const int*   coords = nullptr;
    const float* qkv_w = nullptr;
    const float* qkv_b = nullptr;
    const float* proj_w = nullptr;
    const float* proj_b = nullptr;
    for (int i = 0; i < n_in; ++i) {
        switch (in_sizes[i]) {
            case TOKENS * CC:      x      = (const float*)d_in[i]; break;
            case TOKENS * 3:       coords = (const int*)d_in[i];   break;
            case CC * C3:          qkv_w  = (const float*)d_in[i]; break;
            case C3:               qkv_b  = (const float*)d_in[i]; break;
            case CC * CC:          proj_w = (const float*)d_in[i]; break;
            case CC:               proj_b = (const float*)d_in[i]; break;
            default: break;
        }
    }
    float* out = (float*)d_out;

    float* qkv;
    __nv_bfloat16 *xh, *xl, *ah, *al, *wqh, *wql, *wph, *wpl;
    __nv_bfloat16 *qh, *ql, *kh, *kl, *vth, *vtl;
    cudaGetSymbolAddress((void**)&qkv, g_qkv);
    cudaGetSymbolAddress((void**)&xh,  g_xh);
    cudaGetSymbolAddress((void**)&xl,  g_xl);
    cudaGetSymbolAddress((void**)&ah,  g_ah);
    cudaGetSymbolAddress((void**)&al,  g_al);
    cudaGetSymbolAddress((void**)&wqh, g_wqh);
    cudaGetSymbolAddress((void**)&wql, g_wql);
    cudaGetSymbolAddress((void**)&wph, g_wph);
    cudaGetSymbolAddress((void**)&wpl, g_wpl);
    cudaGetSymbolAddress((void**)&qh,  g_qh);
    cudaGetSymbolAddress((void**)&ql,  g_ql);
    cudaGetSymbolAddress((void**)&kh,  g_kh);
    cudaGetSymbolAddress((void**)&kl,  g_kl);
    cudaGetSymbolAddress((void**)&vth, g_vth);
    cudaGetSymbolAddress((void**)&vtl, g_vtl);

    const int gemm_smem = 3 * STAGE_BYTES;   // 98304
    cudaFuncSetAttribute(mma_gemm_kernel, cudaFuncAttributeMaxDynamicSharedMemorySize, gemm_smem);
    const int attn_smem = 3 * AT_STAGE;      // 178176
    cudaFuncSetAttribute(attn_mma_kernel, cudaFuncAttributeMaxDynamicSharedMemorySize, attn_smem);

    // 1) split x
    convert_split_kernel<<<4096, 256>>>(x, xh, xl, TOKENS * CC);

    // 2) transpose+split qkv_w
    {
        dim3 grid(C3 / 32, CC / 32);
        transpose_split_kernel<<<grid, dim3(32, 8)>>>(qkv_w, wqh, wql, CC, C3);
    }

    // 3) QKV GEMM
    {
        dim3 grid(C3 / 128, TOKENS / 128);
        mma_gemm_kernel<<<grid, 256, gemm_smem>>>(xh, xl, wqh, wql, qkv_b, qkv,
                                                  TOKENS, C3, CC);
    }

    // 4) RoPE + scale + split q/k; transpose+split v
    qk_prep_kernel<<<TOKENS, 128>>>(coords, qkv, qh, ql, kh, kl);
    {
        dim3 grid(NN / 32, (DD + 31) / 32, BB * HH);
        vt_prep_kernel<<<grid, dim3(32, 8)>>>(qkv, vth, vtl);
    }

    // 5) Flash attention on tensor cores -> writes proj inputs (ah/al)
    {
        dim3 grid(NN / 128, HH, BB);
        attn_mma_kernel<<<grid, 256, attn_smem>>>(qh, ql, kh, kl, vth, vtl, ah, al);
    }

    // 6) transpose+split proj_w
    {
        dim3 grid(CC / 32, CC / 32);
        transpose_split_kernel<<<grid, dim3(32, 8)>>>(proj_w, wph, wpl, CC, CC);
    }

    // 7) Projection GEMM
    {
        dim3 grid(CC / 128, TOKENS / 128);
        mma_gemm_kernel<<<grid, 256, gemm_smem>>>(ah, al, wph, wpl, proj_b, out,
                                                  TOKENS, CC, CC);
    }
}